// round 11
// baseline (speedup 1.0000x reference)
#include <cuda_runtime.h>
#include <cuda_fp16.h>
#include <cstdint>

// ============================================================================
// y[t, :] = weight[x[t], :] + A[x[t], :] @ B
//   tokens M = 16384, DIM N = 1024, RANK K = 256
// mma.sync.m16n8k16.f32.f16.f16.f32, 2 CTAs/SM.
// TILE 128x64, KC=128 (2 chunks): only 3 wait points per tile; weight tile
// staged into dead buffer 0, covered by the full second compute span.
// ============================================================================
static constexpr int M_TOTAL = 16384;
static constexpr int DIM     = 1024;
static constexpr int RANK    = 256;

static constexpr int TILE_M  = 128;
static constexpr int TILE_N  = 64;
static constexpr int KC      = 128;             // K chunk (halves)
static constexpr int STAGES  = 2;

// Smem: pitch 136 halves (272 B) -> conflict-free ldmatrix (banks 4r mod 32)
static constexpr int PITCH       = 136;
static constexpr int A_TILE_B    = TILE_M * PITCH * 2;        // 34816 B
static constexpr int B_TILE_B    = TILE_N * PITCH * 2;        // 17408 B
static constexpr int STAGE_BYTES = A_TILE_B + B_TILE_B;       // 52224 B
static constexpr int SMEM_BYTES  = STAGES * STAGE_BYTES + 512; // 104960 B

// Weight staging: 128 rows x 272 B (68 floats) = 34816 B -> fits buffer 0
static constexpr int W_PITCH_F = 68;
static constexpr int W_PITCH_B = 272;

// Scratch: half B^T [DIM][RANK] (0.5 MB), gathered half A [M][RANK] (8 MB)
__device__ __half g_Bt[DIM * RANK];
__device__ __half g_Ah[M_TOTAL * RANK];

// ---------------------------------------------------------------------------
__device__ __forceinline__ uint32_t smem_to_u32(const void* p) {
    uint32_t a;
    asm("{ .reg .u64 t; cvta.to.shared.u64 t, %1; cvt.u32.u64 %0, t; }" : "=r"(a) : "l"(p));
    return a;
}
__device__ __forceinline__ void cp_async16(uint32_t dst, const void* src) {
    asm volatile("cp.async.cg.shared.global [%0], [%1], 16;" :: "r"(dst), "l"(src));
}
__device__ __forceinline__ void cp_commit() {
    asm volatile("cp.async.commit_group;" ::: "memory");
}
template <int N>
__device__ __forceinline__ void cp_wait() {
    asm volatile("cp.async.wait_group %0;" :: "n"(N) : "memory");
}
__device__ __forceinline__ void ldmatrix_x4(uint32_t& r0, uint32_t& r1,
                                            uint32_t& r2, uint32_t& r3, uint32_t addr) {
    asm volatile("ldmatrix.sync.aligned.m8n8.x4.shared.b16 {%0,%1,%2,%3}, [%4];"
                 : "=r"(r0), "=r"(r1), "=r"(r2), "=r"(r3) : "r"(addr));
}
__device__ __forceinline__ void mma_f16(float* c, const uint32_t* a, const uint32_t* b) {
    asm volatile(
        "mma.sync.aligned.m16n8k16.row.col.f32.f16.f16.f32 "
        "{%0,%1,%2,%3}, {%4,%5,%6,%7}, {%8,%9}, {%0,%1,%2,%3};\n"
        : "+f"(c[0]), "+f"(c[1]), "+f"(c[2]), "+f"(c[3])
        : "r"(a[0]), "r"(a[1]), "r"(a[2]), "r"(a[3]), "r"(b[0]), "r"(b[1]));
}
__device__ __forceinline__ void stg_cs_v2(float* p, float x, float y) {
    asm volatile("st.global.cs.v2.f32 [%0], {%1,%2};" :: "l"(p), "f"(x), "f"(y) : "memory");
}

// ============================================================================
// Kernel 1 (fused prep):
//   blocks [0,256):     transpose+convert B -> g_Bt [DIM][RANK] half
//   blocks [256,2304):  gather+convert A rows: g_Ah[t] = half(A[x[t]]), 8 rows/blk
// ============================================================================
__global__ __launch_bounds__(256)
void prep_kernel(const int* __restrict__ x, const float* __restrict__ A,
                 const float* __restrict__ B) {
    if (blockIdx.x < 256) {
        __shared__ float t[32][33];
        const int n0 = (blockIdx.x & 31) * 32;
        const int k0 = (blockIdx.x >> 5) * 32;
        const int tx = threadIdx.x & 31;
        const int ty = threadIdx.x >> 5;
        #pragma unroll
        for (int j = 0; j < 32; j += 8)
            t[ty + j][tx] = B[(size_t)(k0 + ty + j) * DIM + n0 + tx];
        __syncthreads();
        #pragma unroll
        for (int j = 0; j < 32; j += 8)
            g_Bt[(size_t)(n0 + ty + j) * RANK + k0 + tx] = __float2half_rn(t[tx][ty + j]);
    } else {
        const int row  = (blockIdx.x - 256) * 8 + (threadIdx.x >> 5);
        const int lane = threadIdx.x & 31;
        const int tok  = x[row];
        const float4* src = (const float4*)(A + (size_t)tok * RANK) + lane * 2;
        float4 v0 = src[0], v1 = src[1];
        __half2 h[4];
        h[0] = __floats2half2_rn(v0.x, v0.y);
        h[1] = __floats2half2_rn(v0.z, v0.w);
        h[2] = __floats2half2_rn(v1.x, v1.y);
        h[3] = __floats2half2_rn(v1.z, v1.w);
        *(uint4*)(g_Ah + (size_t)row * RANK + lane * 8) = *(const uint4*)h;
    }
#if __CUDA_ARCH__ >= 900
    cudaTriggerProgrammaticLaunchCompletion();
#endif
}

// ============================================================================
// Kernel 2: fused GEMM + weight-gather epilogue
//   grid: (DIM/64 = 16, M/128 = 128) N fastest; block 256 = 8 warps;
//   warp grid 4(M) x 2(N), warp tile 32x32; 2 CTAs/SM.
// ============================================================================
__global__ __launch_bounds__(256, 2)
void lora_embed_kernel(const int* __restrict__ x,
                       const float* __restrict__ weight,
                       float* __restrict__ out) {
    extern __shared__ __align__(16) char smem[];
    int* s_tok = (int*)(smem + STAGES * STAGE_BYTES);

    const int tid    = threadIdx.x;
    const int wid    = tid >> 5;
    const int lane   = tid & 31;
    const int group  = lane >> 2;   // 0..7
    const int tig    = lane & 3;    // 0..3
    const int warp_m = wid >> 1;    // 0..3
    const int warp_n = wid & 1;     // 0..1

    const int n0 = blockIdx.x * TILE_N;
    const int m0 = blockIdx.y * TILE_M;

    if (tid < TILE_M) s_tok[tid] = x[m0 + tid];

    const uint32_t sb = smem_to_u32(smem);

    // Loaders per chunk:
    //   A: 2 threads/row, 64 halves (8 x 16B) each
    //   B: 4 threads/row, 32 halves (4 x 16B) each
    const int arow = tid >> 1, ahalf = tid & 1;
    const int brow = tid >> 2, bq    = tid & 3;
    const __half* a_src = g_Ah + (size_t)(m0 + arow) * RANK + ahalf * 64;
    const __half* b_src = g_Bt + (size_t)(n0 + brow) * RANK + bq * 32;
    const uint32_t a_dst = sb + (arow * PITCH + ahalf * 64) * 2;
    const uint32_t b_dst = sb + (uint32_t)A_TILE_B + (brow * PITCH + bq * 32) * 2;

    auto prefetch = [&](int c) {
        const uint32_t soff = (uint32_t)(c & 1) * STAGE_BYTES;
        #pragma unroll
        for (int i = 0; i < 8; i++)
            cp_async16(a_dst + soff + i * 16, a_src + c * KC + i * 8);
        #pragma unroll
        for (int i = 0; i < 4; i++)
            cp_async16(b_dst + soff + i * 16, b_src + c * KC + i * 8);
        cp_commit();
    };

    // Stage the whole 128x64 weight tile into (dead) buffer 0.
    // 128 rows x 16 x 16B = 2048 units over 256 threads x 8 iters.
    auto stage_weight = [&]() {
        #pragma unroll
        for (int i = 0; i < 8; i++) {
            const int idx = tid + 256 * i;        // 0..2047
            const int row = idx >> 4;             // 0..127
            const int c16 = idx & 15;             // 16B chunk in 256B row
            const int tok = s_tok[row];
            cp_async16(sb + (uint32_t)(row * W_PITCH_B + c16 * 16),
                       weight + (size_t)tok * DIM + n0 + c16 * 4);
        }
        cp_commit();
    };

    float acc[2][4][4];
    #pragma unroll
    for (int mt = 0; mt < 2; mt++)
        #pragma unroll
        for (int nt = 0; nt < 4; nt++)
            #pragma unroll
            for (int r = 0; r < 4; r++) acc[mt][nt][r] = 0.f;

    // A ldmatrix lane offset: row = warp_m*32 + (lane&15), koff = (lane>>4)*8
    const uint32_t a_lane_off =
        (uint32_t)(((warp_m * 32 + (lane & 15)) * PITCH + (lane >> 4) * 8) * 2);
    // B ldmatrix lane offset (x4 = mats [nlo klo, nlo khi, nhi klo, nhi khi])
    const uint32_t b_lane_off =
        (uint32_t)(((warp_n * 32 + ((lane >> 4) << 3) + (lane & 7)) * PITCH
                    + ((lane >> 3) & 1) * 8) * 2);

    auto compute = [&](int c) {
        const uint32_t abuf = sb + (uint32_t)(c & 1) * STAGE_BYTES;
        const uint32_t bbuf = abuf + (uint32_t)A_TILE_B;
        #pragma unroll
        for (int ks = 0; ks < 8; ks++) {
            const uint32_t k0b = (uint32_t)(ks * 32);   // 16 halves * 2B
            uint32_t af[2][4];
            #pragma unroll
            for (int mt = 0; mt < 2; mt++)
                ldmatrix_x4(af[mt][0], af[mt][1], af[mt][2], af[mt][3],
                            abuf + a_lane_off + (uint32_t)(mt * 16 * PITCH * 2) + k0b);
            uint32_t bf[4][2];
            #pragma unroll
            for (int q = 0; q < 2; q++)
                ldmatrix_x4(bf[2 * q][0], bf[2 * q][1], bf[2 * q + 1][0], bf[2 * q + 1][1],
                            bbuf + b_lane_off + (uint32_t)(q * 16 * PITCH * 2) + k0b);
            #pragma unroll
            for (int mt = 0; mt < 2; mt++)
                #pragma unroll
                for (int nt = 0; nt < 4; nt++)
                    mma_f16(acc[mt][nt], af[mt], bf[nt]);
        }
    };

    // PDL: block only before first use of g_Ah/g_Bt.
#if __CUDA_ARCH__ >= 900
    cudaGridDependencySynchronize();
#endif

    // Pipeline: groups G0=pf0, G1=pf1, G2=weight.
    //   wait<1> -> G0 done; compute(0) on buf0.
    //   sync    -> buf0 dead; stage weight into it (G2), covered by compute(1).
    //   wait<1> -> G1 done (G2 outstanding); compute(1) on buf1.
    //   wait<0> -> weight resident; epilogue.
    prefetch(0);
    prefetch(1);

    cp_wait<1>(); __syncthreads(); compute(0);
    __syncthreads(); stage_weight();
    cp_wait<1>(); __syncthreads(); compute(1);
    cp_wait<0>(); __syncthreads();

    // Epilogue: out = weight_smem + acc.
    const float* wsm = (const float*)smem;   // buffer 0 holds the weight tile
    #pragma unroll
    for (int mt = 0; mt < 2; mt++) {
        #pragma unroll
        for (int mo = 0; mo < 2; mo++) {
            const int r = warp_m * 32 + mt * 16 + mo * 8 + group;   // 0..127
            const float* wrow = wsm + r * W_PITCH_F;
            float* orow = out + (size_t)(m0 + r) * DIM + n0;
            #pragma unroll
            for (int nt = 0; nt < 4; nt++) {
                const int col = warp_n * 32 + nt * 8 + tig * 2;
                float2 w = *(const float2*)(wrow + col);
                stg_cs_v2(orow + col,
                          w.x + acc[mt][nt][mo * 2 + 0],
                          w.y + acc[mt][nt][mo * 2 + 1]);
            }
        }
    }
}

// ============================================================================
// Launch
// ============================================================================
extern "C" void kernel_launch(void* const* d_in, const int* in_sizes, int n_in,
                              void* d_out, int out_size) {
    const int*   x      = (const int*)d_in[0];       // [16384] int32
    const float* weight = (const float*)d_in[1];     // [128000, 1024]
    const float* A      = (const float*)d_in[2];     // [128000, 256]
    const float* B      = (const float*)d_in[3];     // [256, 1024]
    float* out          = (float*)d_out;             // [16384, 1024]

    (void)in_sizes; (void)n_in; (void)out_size;

    // Fused prep: 256 transpose blocks + 2048 gather blocks
    prep_kernel<<<256 + M_TOTAL / 8, 256>>>(x, A, B);

    {
        static bool attr_set = false;
        if (!attr_set) {
            cudaFuncSetAttribute(lora_embed_kernel,
                                 cudaFuncAttributeMaxDynamicSharedMemorySize, SMEM_BYTES);
            attr_set = true;
        }
        cudaLaunchConfig_t cfg = {};
        cfg.gridDim  = dim3(DIM / TILE_N, M_TOTAL / TILE_M);   // (16, 128)
        cfg.blockDim = dim3(256, 1, 1);
        cfg.dynamicSmemBytes = SMEM_BYTES;
        cfg.stream = 0;
        cudaLaunchAttribute attrs[1];
        attrs[0].id = cudaLaunchAttributeProgrammaticStreamSerialization;
        attrs[0].val.programmaticStreamSerializationAllowed = 1;
        cfg.attrs = attrs;
        cfg.numAttrs = 1;
        cudaError_t err = cudaLaunchKernelEx(&cfg, lora_embed_kernel, x, weight, out);
        if (err != cudaSuccess) {
            cudaGetLastError();
            dim3 grid(DIM / TILE_N, M_TOTAL / TILE_M);
            lora_embed_kernel<<<grid, 256, SMEM_BYTES>>>(x, weight, out);
        }
    }
}

// round 12
// speedup vs baseline: 1.4745x; 1.4745x over previous
#include <cuda_runtime.h>
#include <cuda_fp16.h>
#include <cstdint>

// ============================================================================
// y[t, :] = weight[x[t], :] + A[x[t], :] @ B
//   tokens M = 16384, DIM N = 1024, RANK K = 256
// A is pre-gathered into MMA-FRAGMENT layout (g_Af[mb][ks][lane] = uint4), so
// the mainloop loads A fragments directly gmem->regs (1 LDG.128, no smem, no
// ldmatrix). B: KC=64 double-buffered smem + ldmatrix. Weight: dedicated smem
// region staged at tile start, forced by the chunk-2 wait (2-chunk cover).
// ============================================================================
static constexpr int M_TOTAL = 16384;
static constexpr int DIM     = 1024;
static constexpr int RANK    = 256;

static constexpr int TILE_M  = 128;
static constexpr int TILE_N  = 128;
static constexpr int KC      = 64;                      // B chunk (halves)

// B smem: pitch 72 halves -> conflict-free ldmatrix (banks 4r mod 32)
static constexpr int PITCH_B    = 72;
static constexpr int B_CHUNK_B  = TILE_N * PITCH_B * 2;   // 18432 B
static constexpr int W_OFF      = 2 * B_CHUNK_B;          // 36864
static constexpr int W_PITCH_F  = 132;                    // floats (528 B)
static constexpr int W_PITCH_BY = 528;
static constexpr int SMEM_BYTES = W_OFF + TILE_M * W_PITCH_BY + 64;  // 104512

// Scratch: half B^T [DIM][RANK] (0.5 MB); A fragments [1024 mb][16 ks][32 lane]
__device__ __half g_Bt[DIM * RANK];
__device__ uint4  g_Af[(M_TOTAL / 16) * 16 * 32];         // 8 MB

// ---------------------------------------------------------------------------
__device__ __forceinline__ uint32_t smem_to_u32(const void* p) {
    uint32_t a;
    asm("{ .reg .u64 t; cvta.to.shared.u64 t, %1; cvt.u32.u64 %0, t; }" : "=r"(a) : "l"(p));
    return a;
}
__device__ __forceinline__ void cp_async16(uint32_t dst, const void* src) {
    asm volatile("cp.async.cg.shared.global [%0], [%1], 16;" :: "r"(dst), "l"(src));
}
__device__ __forceinline__ void cp_commit() {
    asm volatile("cp.async.commit_group;" ::: "memory");
}
template <int N>
__device__ __forceinline__ void cp_wait() {
    asm volatile("cp.async.wait_group %0;" :: "n"(N) : "memory");
}
__device__ __forceinline__ void ldmatrix_x4(uint32_t& r0, uint32_t& r1,
                                            uint32_t& r2, uint32_t& r3, uint32_t addr) {
    asm volatile("ldmatrix.sync.aligned.m8n8.x4.shared.b16 {%0,%1,%2,%3}, [%4];"
                 : "=r"(r0), "=r"(r1), "=r"(r2), "=r"(r3) : "r"(addr));
}
__device__ __forceinline__ void mma_f16(float* c, const uint32_t* a, const uint32_t* b) {
    asm volatile(
        "mma.sync.aligned.m16n8k16.row.col.f32.f16.f16.f32 "
        "{%0,%1,%2,%3}, {%4,%5,%6,%7}, {%8,%9}, {%0,%1,%2,%3};\n"
        : "+f"(c[0]), "+f"(c[1]), "+f"(c[2]), "+f"(c[3])
        : "r"(a[0]), "r"(a[1]), "r"(a[2]), "r"(a[3]), "r"(b[0]), "r"(b[1]));
}
__device__ __forceinline__ void stg_cs_v2(float* p, float x, float y) {
    asm volatile("st.global.cs.v2.f32 [%0], {%1,%2};" :: "l"(p), "f"(x), "f"(y) : "memory");
}
__device__ __forceinline__ uint32_t h2u(float a, float b) {
    __half2 h = __floats2half2_rn(a, b);
    return *(uint32_t*)&h;
}

// ============================================================================
// Kernel 1 (fused prep):
//   blocks [0,256):        transpose+convert B -> g_Bt [DIM][RANK] half
//   blocks [256,256+2048): gather A rows into FRAGMENT layout g_Af.
//     block b: mb = b>>1; warp w handles ks = (b&1)*8 + w; lane l emits the
//     uint4 that mma.m16n8k16 expects: rows (l>>2, l>>2+8) x k (2(l&3), +8).
// ============================================================================
__global__ __launch_bounds__(256)
void prep_kernel(const int* __restrict__ x, const float* __restrict__ A,
                 const float* __restrict__ B) {
    if (blockIdx.x < 256) {
        __shared__ float t[32][33];
        const int n0 = (blockIdx.x & 31) * 32;
        const int k0 = (blockIdx.x >> 5) * 32;
        const int tx = threadIdx.x & 31;
        const int ty = threadIdx.x >> 5;
        #pragma unroll
        for (int j = 0; j < 32; j += 8)
            t[ty + j][tx] = B[(size_t)(k0 + ty + j) * DIM + n0 + tx];
        __syncthreads();
        #pragma unroll
        for (int j = 0; j < 32; j += 8)
            g_Bt[(size_t)(n0 + ty + j) * RANK + k0 + tx] = __float2half_rn(t[tx][ty + j]);
    } else {
        const int blk  = blockIdx.x - 256;                 // 0..2047
        const int mb   = blk >> 1;                         // 0..1023
        const int ks   = ((blk & 1) << 3) + (threadIdx.x >> 5);  // 0..15
        const int lane = threadIdx.x & 31;
        const int r    = lane >> 2;
        const int c    = ks * 16 + (lane & 3) * 2;
        const int tok_lo = x[mb * 16 + r];
        const int tok_hi = x[mb * 16 + 8 + r];
        const float* alo = A + (size_t)tok_lo * RANK;
        const float* ahi = A + (size_t)tok_hi * RANK;
        const float2 f0 = *(const float2*)(alo + c);
        const float2 f1 = *(const float2*)(ahi + c);
        const float2 f2 = *(const float2*)(alo + c + 8);
        const float2 f3 = *(const float2*)(ahi + c + 8);
        uint4 v;
        v.x = h2u(f0.x, f0.y);
        v.y = h2u(f1.x, f1.y);
        v.z = h2u(f2.x, f2.y);
        v.w = h2u(f3.x, f3.y);
        g_Af[(mb * 16 + ks) * 32 + lane] = v;
    }
#if __CUDA_ARCH__ >= 900
    cudaTriggerProgrammaticLaunchCompletion();
#endif
}

// ============================================================================
// Kernel 2: fused GEMM + weight epilogue
//   grid: (8, 128) N fastest; block 256 = 8 warps; warp grid 2(M) x 4(N),
//   warp tile 64x32; 2 CTAs/SM. A fragments: direct LDG.128, 1 k-step ahead.
// ============================================================================
__global__ __launch_bounds__(256, 2)
void lora_embed_kernel(const int* __restrict__ x,
                       const float* __restrict__ weight,
                       float* __restrict__ out) {
    extern __shared__ __align__(16) char smem[];

    const int tid    = threadIdx.x;
    const int wid    = tid >> 5;
    const int lane   = tid & 31;
    const int group  = lane >> 2;   // 0..7
    const int tig    = lane & 3;    // 0..3
    const int warp_m = wid >> 2;    // 0..1
    const int warp_n = wid & 3;     // 0..3

    const int n0 = blockIdx.x * TILE_N;
    const int m0 = blockIdx.y * TILE_M;

    const uint32_t sb = smem_to_u32(smem);

    // B loader: 2 threads/row, 32 halves (4 x 16B) per chunk
    const int brow = tid >> 1, bh = tid & 1;
    const __half* b_src = g_Bt + (size_t)(n0 + brow) * RANK + bh * 32;
    const uint32_t b_dst = sb + (brow * PITCH_B + bh * 32) * 2;

    auto pfB = [&](int c) {
        const uint32_t soff = (uint32_t)(c & 1) * B_CHUNK_B;
        #pragma unroll
        for (int i = 0; i < 4; i++)
            cp_async16(b_dst + soff + i * 16, b_src + c * KC + i * 8);
        cp_commit();
    };

    // Weight stager: 128 rows x 32 x 16B chunks = 4096 units, 16 per thread.
    auto stage_weight = [&]() {
        #pragma unroll
        for (int i = 0; i < 16; i++) {
            const int idx = tid + 256 * i;       // 0..4095
            const int row = idx >> 5;            // 0..127
            const int c16 = idx & 31;            // 16B chunk in 512B row
            const int tok = x[m0 + row];         // 32 threads/row -> broadcast
            cp_async16(sb + (uint32_t)(W_OFF + row * W_PITCH_BY + c16 * 16),
                       weight + (size_t)tok * DIM + n0 + c16 * 4);
        }
        cp_commit();
    };

    // A fragment base: mb_w = m0/16 + warp_m*4; addr(mt,ks) = +mt*8192 + ks*512
    const char* aptr = (const char*)g_Af
        + ((size_t)(blockIdx.y * 8 + warp_m * 4) * 16 * 32 + lane) * 16;

    // B ldmatrix lane offset (x4 = mats [nlo klo, nlo khi, nhi klo, nhi khi])
    const uint32_t b_lane_off =
        (uint32_t)(((warp_n * 32 + ((lane >> 4) << 3) + (lane & 7)) * PITCH_B
                    + ((lane >> 3) & 1) * 8) * 2);

    float acc[4][4][4];
    #pragma unroll
    for (int mt = 0; mt < 4; mt++)
        #pragma unroll
        for (int nt = 0; nt < 4; nt++)
            #pragma unroll
            for (int r = 0; r < 4; r++) acc[mt][nt][r] = 0.f;

    uint4 af[2][4];

    auto load_A = [&](int buf, int ks) {
        #pragma unroll
        for (int mt = 0; mt < 4; mt++)
            af[buf][mt] = *(const uint4*)(aptr + mt * 8192 + ks * 512);
    };

    auto compute = [&](int c) {
        const uint32_t bbuf = sb + (uint32_t)(c & 1) * B_CHUNK_B;
        #pragma unroll
        for (int kl = 0; kl < 4; kl++) {
            const int ksg = c * 4 + kl;
            if (ksg + 1 < 16) load_A((ksg + 1) & 1, ksg + 1);
            uint32_t bf[4][2];
            #pragma unroll
            for (int q = 0; q < 2; q++)
                ldmatrix_x4(bf[2 * q][0], bf[2 * q][1], bf[2 * q + 1][0], bf[2 * q + 1][1],
                            bbuf + b_lane_off + (uint32_t)(q * 16 * PITCH_B * 2)
                                 + (uint32_t)(kl * 32));
            const uint32_t* a = (const uint32_t*)&af[ksg & 1][0];
            #pragma unroll
            for (int mt = 0; mt < 4; mt++)
                #pragma unroll
                for (int nt = 0; nt < 4; nt++)
                    mma_f16(acc[mt][nt], a + mt * 4, bf[nt]);
        }
    };

    // PDL: g_Af / g_Bt produced by prep.
#if __CUDA_ARCH__ >= 900
    cudaGridDependencySynchronize();
#endif

    // Groups: G0=B0 G1=B1 G2=W G3=B2 G4=B3.
    //   wait<2> -> B0; wait<2> -> B1; wait<1> -> B2 (+W, covered by 2 chunks);
    //   wait<0> -> B3. Epilogue needs no wait (W forced at chunk 2).
    pfB(0);
    pfB(1);
    stage_weight();
    load_A(0, 0);

    cp_wait<2>(); __syncthreads(); compute(0);
    __syncthreads(); pfB(2);
    cp_wait<2>(); __syncthreads(); compute(1);
    __syncthreads(); pfB(3);
    cp_wait<1>(); __syncthreads(); compute(2);
    cp_wait<0>(); __syncthreads(); compute(3);

    // Epilogue: out = weight_smem + acc (W region resident since chunk 2).
    const float* wsm = (const float*)(smem + W_OFF);
    #pragma unroll
    for (int mt = 0; mt < 4; mt++) {
        #pragma unroll
        for (int mo = 0; mo < 2; mo++) {
            const int r = warp_m * 64 + mt * 16 + mo * 8 + group;   // 0..127
            const float* wrow = wsm + r * W_PITCH_F;
            float* orow = out + (size_t)(m0 + r) * DIM + n0;
            #pragma unroll
            for (int nt = 0; nt < 4; nt++) {
                const int col = warp_n * 32 + nt * 8 + tig * 2;
                float2 w = *(const float2*)(wrow + col);
                stg_cs_v2(orow + col,
                          w.x + acc[mt][nt][mo * 2 + 0],
                          w.y + acc[mt][nt][mo * 2 + 1]);
            }
        }
    }
}

// ============================================================================
// Launch
// ============================================================================
extern "C" void kernel_launch(void* const* d_in, const int* in_sizes, int n_in,
                              void* d_out, int out_size) {
    const int*   x      = (const int*)d_in[0];       // [16384] int32
    const float* weight = (const float*)d_in[1];     // [128000, 1024]
    const float* A      = (const float*)d_in[2];     // [128000, 256]
    const float* B      = (const float*)d_in[3];     // [256, 1024]
    float* out          = (float*)d_out;             // [16384, 1024]

    (void)in_sizes; (void)n_in; (void)out_size;

    // Fused prep: 256 transpose blocks + 2048 fragment-gather blocks
    prep_kernel<<<256 + 2048, 256>>>(x, A, B);

    {
        static bool attr_set = false;
        if (!attr_set) {
            cudaFuncSetAttribute(lora_embed_kernel,
                                 cudaFuncAttributeMaxDynamicSharedMemorySize, SMEM_BYTES);
            attr_set = true;
        }
        cudaLaunchConfig_t cfg = {};
        cfg.gridDim  = dim3(DIM / TILE_N, M_TOTAL / TILE_M);   // (8, 128)
        cfg.blockDim = dim3(256, 1, 1);
        cfg.dynamicSmemBytes = SMEM_BYTES;
        cfg.stream = 0;
        cudaLaunchAttribute attrs[1];
        attrs[0].id = cudaLaunchAttributeProgrammaticStreamSerialization;
        attrs[0].val.programmaticStreamSerializationAllowed = 1;
        cfg.attrs = attrs;
        cfg.numAttrs = 1;
        cudaError_t err = cudaLaunchKernelEx(&cfg, lora_embed_kernel, x, weight, out);
        if (err != cudaSuccess) {
            cudaGetLastError();
            dim3 grid(DIM / TILE_N, M_TOTAL / TILE_M);
            lora_embed_kernel<<<grid, 256, SMEM_BYTES>>>(x, weight, out);
        }
    }
}

// round 13
// speedup vs baseline: 1.5903x; 1.0786x over previous
#include <cuda_runtime.h>
#include <cuda_fp16.h>
#include <cstdint>

// ============================================================================
// y[t, :] = weight[x[t], :] + A[x[t], :] @ B
//   tokens M = 16384, DIM N = 1024, RANK K = 256
// BOTH operands pre-gathered into MMA-fragment layout:
//   g_Af[mb][ks][lane] = uint4  (A fragments, 8 MB)
//   g_Bf[nb][ks][lane] = uint4  (B fragments, 0.5 MB, L2-resident)
// Mainloop: pure LDG.128 -> mma.m16n8k16, ZERO smem ops, ZERO barriers.
// Weight tile cp.async-staged at tile start, covered by the whole mainloop.
// ============================================================================
static constexpr int M_TOTAL = 16384;
static constexpr int DIM     = 1024;
static constexpr int RANK    = 256;

static constexpr int TILE_M  = 128;
static constexpr int TILE_N  = 128;

// Smem: weight tile only. 128 rows x 528 B (132 floats).
static constexpr int W_PITCH_F  = 132;
static constexpr int W_PITCH_BY = 528;
static constexpr int SMEM_BYTES = TILE_M * W_PITCH_BY + 64;   // 67648 B

// Fragment scratch
__device__ uint4 g_Af[(M_TOTAL / 16) * 16 * 32];   // [mb][ks][lane], 8 MB
__device__ uint4 g_Bf[(DIM / 16) * 16 * 32];       // [nb][ks][lane], 0.5 MB

// ---------------------------------------------------------------------------
__device__ __forceinline__ uint32_t smem_to_u32(const void* p) {
    uint32_t a;
    asm("{ .reg .u64 t; cvta.to.shared.u64 t, %1; cvt.u32.u64 %0, t; }" : "=r"(a) : "l"(p));
    return a;
}
__device__ __forceinline__ void cp_async16(uint32_t dst, const void* src) {
    asm volatile("cp.async.cg.shared.global [%0], [%1], 16;" :: "r"(dst), "l"(src));
}
__device__ __forceinline__ void cp_commit() {
    asm volatile("cp.async.commit_group;" ::: "memory");
}
template <int N>
__device__ __forceinline__ void cp_wait() {
    asm volatile("cp.async.wait_group %0;" :: "n"(N) : "memory");
}
__device__ __forceinline__ void mma_f16(float* c, const uint32_t* a, const uint32_t* b) {
    asm volatile(
        "mma.sync.aligned.m16n8k16.row.col.f32.f16.f16.f32 "
        "{%0,%1,%2,%3}, {%4,%5,%6,%7}, {%8,%9}, {%0,%1,%2,%3};\n"
        : "+f"(c[0]), "+f"(c[1]), "+f"(c[2]), "+f"(c[3])
        : "r"(a[0]), "r"(a[1]), "r"(a[2]), "r"(a[3]), "r"(b[0]), "r"(b[1]));
}
__device__ __forceinline__ void stg_cs_v2(float* p, float x, float y) {
    asm volatile("st.global.cs.v2.f32 [%0], {%1,%2};" :: "l"(p), "f"(x), "f"(y) : "memory");
}
__device__ __forceinline__ uint32_t h2u(float a, float b) {
    __half2 h = __floats2half2_rn(a, b);
    return *(uint32_t*)&h;
}

// ============================================================================
// Kernel 1 (fused prep):
//   blocks [0,64):       B fragmentizer. Block nb: covers n = nb*16..+16,
//                        all K. Coalesced load into padded smem, then each
//                        warp emits fragment uint4s for 2 ks values.
//   blocks [64,64+2048): A fragment gather (as R12).
// Fragment uint4 = (nlo k0k1, nlo k8k9, nhi k0k1, nhi k8k9) for
// lane l: g=l>>2 (n offset), t=l&3 (k0 = ks*16 + 2t).
// ============================================================================
__global__ __launch_bounds__(256)
void prep_kernel(const int* __restrict__ x, const float* __restrict__ A,
                 const float* __restrict__ B) {
    if (blockIdx.x < 64) {
        // ---- B fragmentizer ----
        __shared__ float sB[256 * 20];             // [k][n], pitch 20 floats
        const int nb  = blockIdx.x;
        const int tid = threadIdx.x;
        // Load B[k][nb*16 .. +16], k = tid (coalesced 64B per thread)
        {
            const float4* src = (const float4*)(B + (size_t)tid * DIM + nb * 16);
            float4* dst = (float4*)(sB + tid * 20);
            #pragma unroll
            for (int i = 0; i < 4; i++) dst[i] = src[i];
        }
        __syncthreads();
        const int wid  = tid >> 5;
        const int lane = tid & 31;
        const int g    = lane >> 2;
        const int t    = lane & 3;
        #pragma unroll
        for (int h = 0; h < 2; h++) {
            const int ks = wid + h * 8;            // 0..15
            const int k0 = ks * 16 + 2 * t;
            uint4 v;
            v.x = h2u(sB[(k0 + 0) * 20 + g],     sB[(k0 + 1) * 20 + g]);
            v.y = h2u(sB[(k0 + 8) * 20 + g],     sB[(k0 + 9) * 20 + g]);
            v.z = h2u(sB[(k0 + 0) * 20 + g + 8], sB[(k0 + 1) * 20 + g + 8]);
            v.w = h2u(sB[(k0 + 8) * 20 + g + 8], sB[(k0 + 9) * 20 + g + 8]);
            g_Bf[(nb * 16 + ks) * 32 + lane] = v;
        }
    } else {
        // ---- A fragment gather ----
        const int blk  = blockIdx.x - 64;                  // 0..2047
        const int mb   = blk >> 1;                         // 0..1023
        const int ks   = ((blk & 1) << 3) + (threadIdx.x >> 5);  // 0..15
        const int lane = threadIdx.x & 31;
        const int r    = lane >> 2;
        const int c    = ks * 16 + (lane & 3) * 2;
        const int tok_lo = x[mb * 16 + r];
        const int tok_hi = x[mb * 16 + 8 + r];
        const float* alo = A + (size_t)tok_lo * RANK;
        const float* ahi = A + (size_t)tok_hi * RANK;
        const float2 f0 = *(const float2*)(alo + c);
        const float2 f1 = *(const float2*)(ahi + c);
        const float2 f2 = *(const float2*)(alo + c + 8);
        const float2 f3 = *(const float2*)(ahi + c + 8);
        uint4 v;
        v.x = h2u(f0.x, f0.y);
        v.y = h2u(f1.x, f1.y);
        v.z = h2u(f2.x, f2.y);
        v.w = h2u(f3.x, f3.y);
        g_Af[(mb * 16 + ks) * 32 + lane] = v;
    }
#if __CUDA_ARCH__ >= 900
    cudaTriggerProgrammaticLaunchCompletion();
#endif
}

// ============================================================================
// Kernel 2: fused GEMM + weight epilogue
//   grid: (8, 128) N fastest; block 256 = 8 warps; warp grid 2(M) x 4(N),
//   warp tile 64x32; 2 CTAs/SM. Mainloop: LDG fragments + MMA, no barriers.
// ============================================================================
__global__ __launch_bounds__(256, 2)
void lora_embed_kernel(const int* __restrict__ x,
                       const float* __restrict__ weight,
                       float* __restrict__ out) {
    extern __shared__ __align__(16) char smem[];

    const int tid    = threadIdx.x;
    const int wid    = tid >> 5;
    const int lane   = tid & 31;
    const int group  = lane >> 2;   // 0..7
    const int tig    = lane & 3;    // 0..3
    const int warp_m = wid >> 2;    // 0..1
    const int warp_n = wid & 3;     // 0..3

    const int n0 = blockIdx.x * TILE_N;
    const int m0 = blockIdx.y * TILE_M;

    const uint32_t sb = smem_to_u32(smem);

    // Weight stager: 128 rows x 32 x 16B chunks = 4096 units, 16 per thread.
    auto stage_weight = [&]() {
        #pragma unroll
        for (int i = 0; i < 16; i++) {
            const int idx = tid + 256 * i;       // 0..4095
            const int row = idx >> 5;            // 0..127
            const int c16 = idx & 31;            // 16B chunk in 512B row
            const int tok = x[m0 + row];         // 32 threads/row -> broadcast
            cp_async16(sb + (uint32_t)(row * W_PITCH_BY + c16 * 16),
                       weight + (size_t)tok * DIM + n0 + c16 * 4);
        }
        cp_commit();
    };

    // Fragment pointers. Both arrays: ks stride 512 B; tile-index stride 8192 B.
    const char* aptr = (const char*)g_Af
        + ((size_t)(blockIdx.y * 8 + warp_m * 4) * 16 * 32 + lane) * 16;
    const char* bptr = (const char*)g_Bf
        + ((size_t)(blockIdx.x * 8 + warp_n * 2) * 16 * 32 + lane) * 16;

    float acc[4][4][4];
    #pragma unroll
    for (int mt = 0; mt < 4; mt++)
        #pragma unroll
        for (int nt = 0; nt < 4; nt++)
            #pragma unroll
            for (int r = 0; r < 4; r++) acc[mt][nt][r] = 0.f;

    uint4 af[2][4];
    uint4 bv[2][2];

    auto load_frags = [&](int buf, int ks) {
        #pragma unroll
        for (int mt = 0; mt < 4; mt++)
            af[buf][mt] = *(const uint4*)(aptr + mt * 8192 + ks * 512);
        #pragma unroll
        for (int q = 0; q < 2; q++)
            bv[buf][q] = *(const uint4*)(bptr + q * 8192 + ks * 512);
    };

    // Start the weight staging (its latency is covered by the whole mainloop).
    stage_weight();

    // PDL: block before first read of g_Af/g_Bf.
#if __CUDA_ARCH__ >= 900
    cudaGridDependencySynchronize();
#endif

    load_frags(0, 0);

    // Mainloop: 16 k-steps, software-pipelined one step ahead, zero barriers.
    #pragma unroll
    for (int ks = 0; ks < 16; ks++) {
        if (ks + 1 < 16) load_frags((ks + 1) & 1, ks + 1);
        const uint32_t* a = (const uint32_t*)&af[ks & 1][0];
        #pragma unroll
        for (int q = 0; q < 2; q++) {
            const uint32_t* bp = (const uint32_t*)&bv[ks & 1][q];
            #pragma unroll
            for (int mt = 0; mt < 4; mt++) {
                mma_f16(acc[mt][2 * q + 0], a + mt * 4, bp + 0);
                mma_f16(acc[mt][2 * q + 1], a + mt * 4, bp + 2);
            }
        }
    }

    // Weight must be resident now (staged ~whole mainloop ago).
    cp_wait<0>();
    __syncthreads();

    // Epilogue: out = weight_smem + acc.
    const float* wsm = (const float*)smem;
    #pragma unroll
    for (int mt = 0; mt < 4; mt++) {
        #pragma unroll
        for (int mo = 0; mo < 2; mo++) {
            const int r = warp_m * 64 + mt * 16 + mo * 8 + group;   // 0..127
            const float* wrow = wsm + r * W_PITCH_F;
            float* orow = out + (size_t)(m0 + r) * DIM + n0;
            #pragma unroll
            for (int nt = 0; nt < 4; nt++) {
                const int col = warp_n * 32 + nt * 8 + tig * 2;
                float2 w = *(const float2*)(wrow + col);
                stg_cs_v2(orow + col,
                          w.x + acc[mt][nt][mo * 2 + 0],
                          w.y + acc[mt][nt][mo * 2 + 1]);
            }
        }
    }
}

// ============================================================================
// Launch
// ============================================================================
extern "C" void kernel_launch(void* const* d_in, const int* in_sizes, int n_in,
                              void* d_out, int out_size) {
    const int*   x      = (const int*)d_in[0];       // [16384] int32
    const float* weight = (const float*)d_in[1];     // [128000, 1024]
    const float* A      = (const float*)d_in[2];     // [128000, 256]
    const float* B      = (const float*)d_in[3];     // [256, 1024]
    float* out          = (float*)d_out;             // [16384, 1024]

    (void)in_sizes; (void)n_in; (void)out_size;

    // Fused prep: 64 B-fragment blocks + 2048 A-fragment blocks
    prep_kernel<<<64 + 2048, 256>>>(x, A, B);

    {
        static bool attr_set = false;
        if (!attr_set) {
            cudaFuncSetAttribute(lora_embed_kernel,
                                 cudaFuncAttributeMaxDynamicSharedMemorySize, SMEM_BYTES);
            attr_set = true;
        }
        cudaLaunchConfig_t cfg = {};
        cfg.gridDim  = dim3(DIM / TILE_N, M_TOTAL / TILE_M);   // (8, 128)
        cfg.blockDim = dim3(256, 1, 1);
        cfg.dynamicSmemBytes = SMEM_BYTES;
        cfg.stream = 0;
        cudaLaunchAttribute attrs[1];
        attrs[0].id = cudaLaunchAttributeProgrammaticStreamSerialization;
        attrs[0].val.programmaticStreamSerializationAllowed = 1;
        cfg.attrs = attrs;
        cfg.numAttrs = 1;
        cudaError_t err = cudaLaunchKernelEx(&cfg, lora_embed_kernel, x, weight, out);
        if (err != cudaSuccess) {
            cudaGetLastError();
            dim3 grid(DIM / TILE_N, M_TOTAL / TILE_M);
            lora_embed_kernel<<<grid, 256, SMEM_BYTES>>>(x, weight, out);
        }
    }
}